// round 10
// baseline (speedup 1.0000x reference)
#include <cuda_runtime.h>
#include <cuda_bf16.h>
#include <cstdint>

#define HH 128
#define WW 128
#define CH 64
#define BATCH 4
#define EPS 1e-5f

// ---------------- scratch (no mallocs allowed) ----------------
__device__ __align__(16) float g_xnhwc[BATCH*HH*WW*CH];
__device__ __align__(16) float g_y1   [BATCH*HH*WW*CH];
__device__ __align__(16) float g_off  [BATCH*HH*WW*18];   // layout [bh][18][128]
__device__ __align__(1024) __nv_bfloat16 g_wtb1[9*2*64*64];
__device__ __align__(1024) __nv_bfloat16 g_wtb2[9*2*64*64];
__device__ __align__(1024) __nv_bfloat16 g_wob1[9*2*32*64];
__device__ __align__(1024) __nv_bfloat16 g_wob2[9*2*32*64];
__device__ __align__(16) float g_bn[256];

// ---------------- helpers ----------------
static __device__ __forceinline__ uint32_t smem_to_u32(const void* p){
    uint32_t a;
    asm("{ .reg .u64 t; cvta.to.shared.u64 t, %1; cvt.u32.u64 %0, t; }" : "=r"(a) : "l"(p));
    return a;
}
#define SWZ128(o) ((o) ^ (((o) >> 3) & 0x70))

#define LDSM4(r, a) \
    asm volatile("ldmatrix.sync.aligned.m8n8.x4.shared.b16 {%0,%1,%2,%3}, [%4];" \
        : "=r"((r)[0]), "=r"((r)[1]), "=r"((r)[2]), "=r"((r)[3]) : "r"(a))

static __device__ __forceinline__ void mma16816(float* d, const uint32_t* a, uint32_t b0, uint32_t b1){
    asm volatile("mma.sync.aligned.m16n8k16.row.col.f32.bf16.bf16.f32 "
        "{%0,%1,%2,%3},{%4,%5,%6,%7},{%8,%9},{%0,%1,%2,%3};"
        : "+f"(d[0]), "+f"(d[1]), "+f"(d[2]), "+f"(d[3])
        : "r"(a[0]), "r"(a[1]), "r"(a[2]), "r"(a[3]), "r"(b0), "r"(b1));
}

#define CP_ASYNC16(dst, src) \
    asm volatile("cp.async.cg.shared.global [%0], [%1], 16;" :: "r"(dst), "l"(src) : "memory")
#define CP_COMMIT() asm volatile("cp.async.commit_group;" ::: "memory")
#define CP_WAIT0()  asm volatile("cp.async.wait_group 0;" ::: "memory")

#define BAR_SYNC(id, cnt)   asm volatile("bar.sync %0, %1;"   :: "r"(id), "r"(cnt) : "memory")
#define BAR_ARRIVE(id, cnt) asm volatile("bar.arrive %0, %1;" :: "r"(id), "r"(cnt) : "memory")

// ---------------- prep ----------------
__global__ void k_prep(const float* __restrict__ w1, const float* __restrict__ w2,
                       const float* __restrict__ woff1, const float* __restrict__ woff2,
                       const float* g1, const float* be1, const float* m1, const float* v1,
                       const float* g2, const float* be2, const float* m2, const float* v2)
{
    int i = blockIdx.x*blockDim.x + threadIdx.x;
    if(i < 73728){
        int L   = i / 36864;
        int rem = i % 36864;
        int k = rem >> 12;
        int o = (rem >> 6) & 63;
        int c = rem & 63;
        const float* w = L ? w2 : w1;
        float val = w[(o*64 + c)*9 + k];
        __nv_bfloat16 hb = __float2bfloat16(val);
        float hf = __bfloat162float(hb);
        __nv_bfloat16 mb = __float2bfloat16(val - hf);
        char* dst = (char*)(L ? g_wtb2 : g_wtb1);
        int sw = SWZ128(o*128 + c*2);
        *(__nv_bfloat16*)(dst + k*16384 +        sw) = hb;
        *(__nv_bfloat16*)(dst + k*16384 + 8192 + sw) = mb;
    } else if(i < 110592){
        int j   = i - 73728;
        int L   = j / 18432;
        int rem = j % 18432;
        int k = rem >> 11;
        int o = (rem >> 6) & 31;
        int c = rem & 63;
        const float* w = L ? woff2 : woff1;
        float val = (o < 18) ? w[(o*64 + c)*9 + k] : 0.f;
        __nv_bfloat16 hb = __float2bfloat16(val);
        float hf = __bfloat162float(hb);
        __nv_bfloat16 mb = __float2bfloat16(val - hf);
        char* dst = (char*)(L ? g_wob2 : g_wob1);
        int sw = SWZ128(o*128 + c*2);
        *(__nv_bfloat16*)(dst + k*8192 +        sw) = hb;
        *(__nv_bfloat16*)(dst + k*8192 + 4096 + sw) = mb;
    }
    if(blockIdx.x == 0 && threadIdx.x < 64){
        int t = threadIdx.x;
        float i1 = g1[t] * rsqrtf(v1[t] + EPS);
        g_bn[t]      = i1;
        g_bn[64+t]   = be1[t] - m1[t]*i1;
        float i2 = g2[t] * rsqrtf(v2[t] + EPS);
        g_bn[128+t]  = i2;
        g_bn[192+t]  = be2[t] - m2[t]*i2;
    }
}

// ---------------- NCHW -> NHWC transpose ----------------
__global__ void k_nchw2nhwc(const float* __restrict__ x, float* __restrict__ xn){
    __shared__ float tile[64*129];
    int b = blockIdx.x >> 7;
    int h = blockIdx.x & 127;
    const float* src = x + (b*CH*HH)*WW + h*WW;
    for(int i = threadIdx.x; i < CH*WW; i += blockDim.x){
        int c = i >> 7, w = i & 127;
        tile[c*129 + w] = src[c*HH*WW + w];
    }
    __syncthreads();
    float* dst = xn + ((b*HH + h)*WW)*CH;
    for(int i = threadIdx.x; i < CH*WW; i += blockDim.x){
        int w = i >> 6, c = i & 63;
        dst[w*CH + c] = tile[c*129 + w];
    }
}

// ---------------- offset conv v2 (unchanged) ----------------
#define OT2_A_HI  0
#define OT2_A_MID 16640
#define OT2_B     33280
#define OT2_SMEM  49664

__global__ void __launch_bounds__(256,3) k_offt(
    const float* __restrict__ xn, const __nv_bfloat16* __restrict__ wob,
    const float* __restrict__ boff, float* __restrict__ off)
{
    extern __shared__ char smc[];
    const uint32_t smem_base = smem_to_u32(smc);

    const int b = blockIdx.x >> 7;
    const int h = blockIdx.x & 127;
    const int tid = threadIdx.x;
    const int wid = tid >> 5;
    const int lid = tid & 31;
    const int m0 = wid * 16;

    const uint32_t aKh = (lid >> 4) * 16;
    const int aR = m0 + (lid & 15);
    uint32_t bRow[2], bXor[2];
    #pragma unroll
    for(int ni = 0; ni < 2; ni++){
        int r = ni*16 + (lid & 7) + ((lid >> 4) << 3);
        bRow[ni] = r*128;
        bXor[ni] = (r & 7) << 4;
    }
    const uint32_t bKh = ((lid >> 3) & 1) * 16;

    float acc[3][4];
    #pragma unroll
    for(int n8 = 0; n8 < 3; n8++)
        #pragma unroll
        for(int j = 0; j < 4; j++) acc[n8][j] = 0.f;

    {
        const char* bs = (const char*)wob;
        #pragma unroll
        for(int j = 0; j < 2; j++)
            CP_ASYNC16(smem_base + OT2_B + tid*16 + j*4096, bs + tid*16 + j*4096);
        CP_COMMIT();
    }

    #pragma unroll 1
    for(int ky = 0; ky < 3; ky++){
        __syncthreads();
        const int hh = h + ky - 1;
        const bool hv = (hh >= 0) && (hh < HH);
        const float* rowp = xn + (size_t)(b*HH + hh)*WW*CH;
        #pragma unroll 1
        for(int idx = tid; idx < 2080; idx += 256){
            int rho = idx >> 4, q = idx & 15;
            int px = rho - 1;
            float4 v = make_float4(0.f,0.f,0.f,0.f);
            if(hv && px >= 0 && px < WW)
                v = __ldg((const float4*)(rowp + px*CH) + q);
            __nv_bfloat162 h0 = __float22bfloat162_rn(make_float2(v.x, v.y));
            __nv_bfloat162 h1 = __float22bfloat162_rn(make_float2(v.z, v.w));
            float2 f0 = __bfloat1622float2(h0);
            float2 f1 = __bfloat1622float2(h1);
            __nv_bfloat162 m0b = __float22bfloat162_rn(make_float2(v.x - f0.x, v.y - f0.y));
            __nv_bfloat162 m1b = __float22bfloat162_rn(make_float2(v.z - f1.x, v.w - f1.y));
            int sw = SWZ128(rho*128 + q*8);
            uint2 uh, um;
            uh.x = *(uint32_t*)&h0;  uh.y = *(uint32_t*)&h1;
            um.x = *(uint32_t*)&m0b; um.y = *(uint32_t*)&m1b;
            *(uint2*)(smc + OT2_A_HI  + sw) = uh;
            *(uint2*)(smc + OT2_A_MID + sw) = um;
        }

        #pragma unroll 1
        for(int kx = 0; kx < 3; kx++){
            int k = ky*3 + kx;
            CP_WAIT0();
            __syncthreads();
            if(k < 8){
                const char* bs = (const char*)wob + (k+1)*8192;
                uint32_t bd = smem_base + OT2_B + ((k+1)&1)*8192;
                #pragma unroll
                for(int j = 0; j < 2; j++)
                    CP_ASYNC16(bd + tid*16 + j*4096, bs + tid*16 + j*4096);
                CP_COMMIT();
            }
            const uint32_t slotB = smem_base + OT2_B + (k&1)*8192;
            const int rho = aR + 1 + kx - 1;
            const uint32_t aAddrBase = smem_base + OT2_A_HI + rho*128;
            const uint32_t aXor = (rho & 7) << 4;

            #pragma unroll
            for(int ks = 0; ks < 4; ks++){
                uint32_t ahi[4], ami[4], bhi[2][4], bmi[2][4];
                uint32_t ad = aAddrBase + ((ks*32 + aKh) ^ aXor);
                LDSM4(ahi, ad);
                LDSM4(ami, ad + (OT2_A_MID - OT2_A_HI));
                uint32_t cb = ks*32 + bKh;
                #pragma unroll
                for(int ni = 0; ni < 2; ni++){
                    uint32_t bd = slotB + bRow[ni] + (cb ^ bXor[ni]);
                    LDSM4(bhi[ni], bd);
                    LDSM4(bmi[ni], bd + 4096);
                }
                #pragma unroll
                for(int n8 = 0; n8 < 3; n8++){
                    uint32_t bh0 = bhi[n8>>1][(n8&1)*2], bh1 = bhi[n8>>1][(n8&1)*2+1];
                    uint32_t bm0 = bmi[n8>>1][(n8&1)*2], bm1 = bmi[n8>>1][(n8&1)*2+1];
                    mma16816(acc[n8], ahi, bh0, bh1);
                    mma16816(acc[n8], ahi, bm0, bm1);
                    mma16816(acc[n8], ami, bh0, bh1);
                }
            }
        }
    }

    const int r0 = m0 + (lid >> 2);
    const int r1 = r0 + 8;
    float* base = off + (size_t)(b*HH + h)*2304;
    #pragma unroll
    for(int n8 = 0; n8 < 3; n8++){
        int c0 = n8*8 + (lid & 3)*2;
        if(c0 < 18){
            float b0 = __ldg(boff + c0);
            float b1v = __ldg(boff + c0 + 1);
            base[c0*128 + r0]     = acc[n8][0] + b0;
            base[(c0+1)*128 + r0] = acc[n8][1] + b1v;
            base[c0*128 + r1]     = acc[n8][2] + b0;
            base[(c0+1)*128 + r1] = acc[n8][3] + b1v;
        }
    }
}

// ---------------- main DCN v8: warp-specialized producer/consumer ----------------
// 384 threads: warps 0-7 consumers (MMA), warps 8-11 producers (gather + B cp.async).
// Named barriers (count 384): 1=FULL0 2=FULL1 (prod arrive / cons sync),
//                             3=FREE0 4=FREE1 (cons arrive / prod sync).
#define TBW_OFF   0          /* float2 wtab[1152] = 9216 */
#define TBI_OFF   9216       /* uint   itab[1152] = 4608 */
#define A_OFF     13824      /* 2 x (hi 16384 + mid 16384) */
#define B_OFF     79360      /* 2 x (hi 8192 + mid 8192) */
#define DCN_SMEM  112128

template<bool NCHW_OUT>
__global__ void __launch_bounds__(384,2) k_dcn(
    const float* __restrict__ xn, const float* __restrict__ off,
    const __nv_bfloat16* __restrict__ wtb, const float* __restrict__ bn,
    float* __restrict__ out)
{
    extern __shared__ char smc[];
    const uint32_t smem_base = smem_to_u32(smc);

    const int b = blockIdx.x >> 7;
    const int h = blockIdx.x & 127;
    const int tid = threadIdx.x;
    const int wid = tid >> 5;
    const int lid = tid & 31;
    const float fh = (float)h;

    // ---------- build gather table (all 384 threads) ----------
    {
        float2*   wt = (float2*)(smc + TBW_OFF);
        uint32_t* it = (uint32_t*)(smc + TBI_OFF);
        const float* offb2 = off + (size_t)(b*HH + h)*2304;
        #pragma unroll 1
        for(int e = tid; e < 1152; e += 384){
            int k  = e >> 7;
            int px = e & 127;
            float dy = __ldg(offb2 + (2*k)*128 + px);
            float dx = __ldg(offb2 + (2*k+1)*128 + px);
            float py  = fh + (float)(k/3 - 1) + dy;
            float pxx = (float)(px + k%3 - 1) + dx;
            float y0f = floorf(py), x0f = floorf(pxx);
            float wy1 = py - y0f,  wx1 = pxx - x0f;
            bool vy0 = (y0f >= 0.f)  && (y0f <= 127.f);
            bool vy1 = (y0f >= -1.f) && (y0f <= 126.f);
            bool vx0 = (x0f >= 0.f)  && (x0f <= 127.f);
            bool vx1 = (x0f >= -1.f) && (x0f <= 126.f);
            uint32_t yi0 = (uint32_t)(int)fminf(fmaxf(y0f,      0.f),127.f);
            uint32_t yi1 = (uint32_t)(int)fminf(fmaxf(y0f + 1.f,0.f),127.f);
            uint32_t xi0 = (uint32_t)(int)fminf(fmaxf(x0f,      0.f),127.f);
            uint32_t xi1 = (uint32_t)(int)fminf(fmaxf(x0f + 1.f,0.f),127.f);
            wt[e] = make_float2(wy1, wx1);
            it[e] = yi0 | (yi1 << 7) | (xi0 << 14) | (xi1 << 21)
                  | (vy0 ? 1u<<28 : 0u) | (vy1 ? 1u<<29 : 0u)
                  | (vx0 ? 1u<<30 : 0u) | (vx1 ? 1u<<31 : 0u);
        }
    }
    __syncthreads();

    if(wid >= 8){
        // ================= PRODUCER (warps 8-11, 128 threads) =================
        const int ptid = tid - 256;
        const int q  = ptid & 15;
        const int pg = ptid >> 4;          // 0..7 -> 16 px each
        const char* xq = (const char*)(xn + (size_t)b*HH*WW*CH) + q*16;
        const float2*   wt = (const float2*)(smc + TBW_OFF);
        const uint32_t* it = (const uint32_t*)(smc + TBI_OFF);

        #pragma unroll 1
        for(int k = 0; k < 9; k++){
            const int par = k & 1;
            if(k >= 2) BAR_SYNC(3 + par, 384);
            // cp.async B(k) into slot par
            {
                const char* bs = (const char*)wtb + k*16384;
                uint32_t bd = smem_base + B_OFF + par*16384 + ptid*16;
                #pragma unroll
                for(int j = 0; j < 8; j++)
                    CP_ASYNC16(bd + j*2048, bs + ptid*16 + j*2048);
                CP_COMMIT();
            }
            // gather A(k) into buf par
            char* ab = smc + A_OFF + par*32768;
            #pragma unroll 4
            for(int i = 0; i < 16; i++){
                int px = pg*16 + i;
                int e  = k*128 + px;
                float2 t = wt[e];
                uint32_t ii = it[e];
                float ay0 = (ii & (1u<<28)) ? (1.f - t.x) : 0.f;
                float ay1 = (ii & (1u<<29)) ? t.x : 0.f;
                float ax0 = (ii & (1u<<30)) ? (1.f - t.y) : 0.f;
                float ax1 = (ii & (1u<<31)) ? t.y : 0.f;
                uint32_t ry0 = (ii & 0x7fu) << 15;
                uint32_t ry1 = ((ii >> 7) & 0x7fu) << 15;
                uint32_t rx0 = ((ii >> 14) & 0x7fu) << 8;
                uint32_t rx1 = ((ii >> 21) & 0x7fu) << 8;
                float w00 = ay0*ax0, w01 = ay0*ax1, w10 = ay1*ax0, w11 = ay1*ax1;
                float4 a  = __ldg((const float4*)(xq + ry0 + rx0));
                float4 b2 = __ldg((const float4*)(xq + ry0 + rx1));
                float4 c  = __ldg((const float4*)(xq + ry1 + rx0));
                float4 d  = __ldg((const float4*)(xq + ry1 + rx1));
                float4 r;
                r.x = w00*a.x + w01*b2.x + w10*c.x + w11*d.x;
                r.y = w00*a.y + w01*b2.y + w10*c.y + w11*d.y;
                r.z = w00*a.z + w01*b2.z + w10*c.z + w11*d.z;
                r.w = w00*a.w + w01*b2.w + w10*c.w + w11*d.w;
                __nv_bfloat162 h0 = __float22bfloat162_rn(make_float2(r.x, r.y));
                __nv_bfloat162 h1 = __float22bfloat162_rn(make_float2(r.z, r.w));
                float2 f0 = __bfloat1622float2(h0);
                float2 f1 = __bfloat1622float2(h1);
                __nv_bfloat162 m0b = __float22bfloat162_rn(make_float2(r.x - f0.x, r.y - f0.y));
                __nv_bfloat162 m1b = __float22bfloat162_rn(make_float2(r.z - f1.x, r.w - f1.y));
                int sw = SWZ128(px*128 + q*8);
                uint2 uh, um;
                uh.x = *(uint32_t*)&h0;  uh.y = *(uint32_t*)&h1;
                um.x = *(uint32_t*)&m0b; um.y = *(uint32_t*)&m1b;
                *(uint2*)(ab + sw)         = uh;
                *(uint2*)(ab + 16384 + sw) = um;
            }
            CP_WAIT0();
            BAR_ARRIVE(1 + par, 384);
        }
    } else {
        // ================= CONSUMER (warps 0-7, 256 threads) =================
        const int m0 = (wid >> 1) * 32;
        const int n0 = (wid & 1) * 32;

        uint32_t aRow[2], aXor[2];
        #pragma unroll
        for(int mi = 0; mi < 2; mi++){
            int r = m0 + mi*16 + (lid & 15);
            aRow[mi] = r*128;
            aXor[mi] = (r & 7) << 4;
        }
        const uint32_t aKh = (lid >> 4) * 16;
        uint32_t bRow[2], bXor[2];
        #pragma unroll
        for(int ni = 0; ni < 2; ni++){
            int r = n0 + ni*16 + (lid & 7) + ((lid >> 4) << 3);
            bRow[ni] = r*128;
            bXor[ni] = (r & 7) << 4;
        }
        const uint32_t bKh = ((lid >> 3) & 1) * 16;

        float acc[2][4][4];
        #pragma unroll
        for(int mi = 0; mi < 2; mi++)
            #pragma unroll
            for(int ni = 0; ni < 4; ni++)
                #pragma unroll
                for(int j = 0; j < 4; j++) acc[mi][ni][j] = 0.f;

        #pragma unroll 1
        for(int k = 0; k < 9; k++){
            const int par = k & 1;
            BAR_SYNC(1 + par, 384);
            const uint32_t aB    = smem_base + A_OFF + par*32768;
            const uint32_t slotB = smem_base + B_OFF + par*16384;

            #pragma unroll
            for(int ks = 0; ks < 4; ks++){
                uint32_t ca = ks*32 + aKh;
                uint32_t cb = ks*32 + bKh;
                uint32_t ah[2][4], bh[2][4];
                #pragma unroll
                for(int mi = 0; mi < 2; mi++)
                    LDSM4(ah[mi], aB + aRow[mi] + (ca ^ aXor[mi]));
                #pragma unroll
                for(int ni = 0; ni < 2; ni++)
                    LDSM4(bh[ni], slotB + bRow[ni] + (cb ^ bXor[ni]));
                #pragma unroll
                for(int mi = 0; mi < 2; mi++)
                    #pragma unroll
                    for(int n8 = 0; n8 < 4; n8++)
                        mma16816(acc[mi][n8], ah[mi], bh[n8>>1][(n8&1)*2], bh[n8>>1][(n8&1)*2+1]);
                {
                    uint32_t am[2][4];
                    #pragma unroll
                    for(int mi = 0; mi < 2; mi++)
                        LDSM4(am[mi], aB + 16384 + aRow[mi] + (ca ^ aXor[mi]));
                    #pragma unroll
                    for(int mi = 0; mi < 2; mi++)
                        #pragma unroll
                        for(int n8 = 0; n8 < 4; n8++)
                            mma16816(acc[mi][n8], am[mi], bh[n8>>1][(n8&1)*2], bh[n8>>1][(n8&1)*2+1]);
                }
                {
                    uint32_t bm[2][4];
                    #pragma unroll
                    for(int ni = 0; ni < 2; ni++)
                        LDSM4(bm[ni], slotB + 8192 + bRow[ni] + (cb ^ bXor[ni]));
                    #pragma unroll
                    for(int mi = 0; mi < 2; mi++)
                        #pragma unroll
                        for(int n8 = 0; n8 < 4; n8++)
                            mma16816(acc[mi][n8], ah[mi], bm[n8>>1][(n8&1)*2], bm[n8>>1][(n8&1)*2+1]);
                }
            }
            BAR_ARRIVE(3 + par, 384);
        }

        // epilogue: BN + ReLU + store (consumers only)
        #pragma unroll
        for(int mi = 0; mi < 2; mi++){
            int r0 = m0 + mi*16 + (lid >> 2);
            int r1 = r0 + 8;
            #pragma unroll
            for(int n8 = 0; n8 < 4; n8++){
                int c0 = n0 + n8*8 + (lid & 3)*2;
                float iv0 = __ldg(bn + c0),      iv1 = __ldg(bn + c0 + 1);
                float bc0 = __ldg(bn + 64 + c0), bc1 = __ldg(bn + 64 + c0 + 1);
                float v00 = fmaxf(acc[mi][n8][0]*iv0 + bc0, 0.f);
                float v01 = fmaxf(acc[mi][n8][1]*iv1 + bc1, 0.f);
                float v10 = fmaxf(acc[mi][n8][2]*iv0 + bc0, 0.f);
                float v11 = fmaxf(acc[mi][n8][3]*iv1 + bc1, 0.f);
                if(NCHW_OUT){
                    float* o0 = out + (((size_t)b*CH + c0)*HH + h)*WW;
                    float* o1 = out + (((size_t)b*CH + c0+1)*HH + h)*WW;
                    o0[r0] = v00; o1[r0] = v01;
                    o0[r1] = v10; o1[r1] = v11;
                } else {
                    float* base = out + ((size_t)(b*HH + h)*WW)*CH;
                    *(float2*)(base + r0*CH + c0) = make_float2(v00, v01);
                    *(float2*)(base + r1*CH + c0) = make_float2(v10, v11);
                }
            }
        }
    }
}

// ---------------- launcher ----------------
extern "C" void kernel_launch(void* const* d_in, const int* in_sizes, int n_in,
                              void* d_out, int out_size)
{
    const float* x     = (const float*)d_in[0];
    const float* woff1 = (const float*)d_in[1];
    const float* boff1 = (const float*)d_in[2];
    const float* w1    = (const float*)d_in[3];
    const float* g1    = (const float*)d_in[4];
    const float* be1   = (const float*)d_in[5];
    const float* m1    = (const float*)d_in[6];
    const float* v1    = (const float*)d_in[7];
    const float* woff2 = (const float*)d_in[8];
    const float* boff2 = (const float*)d_in[9];
    const float* w2    = (const float*)d_in[10];
    const float* g2    = (const float*)d_in[11];
    const float* be2   = (const float*)d_in[12];
    const float* m2    = (const float*)d_in[13];
    const float* v2    = (const float*)d_in[14];
    float* out = (float*)d_out;

    float *xn, *y1, *offb, *bn;
    __nv_bfloat16 *wtb1, *wtb2, *wob1, *wob2;
    cudaGetSymbolAddress((void**)&xn,   g_xnhwc);
    cudaGetSymbolAddress((void**)&y1,   g_y1);
    cudaGetSymbolAddress((void**)&offb, g_off);
    cudaGetSymbolAddress((void**)&wtb1, g_wtb1);
    cudaGetSymbolAddress((void**)&wtb2, g_wtb2);
    cudaGetSymbolAddress((void**)&wob1, g_wob1);
    cudaGetSymbolAddress((void**)&wob2, g_wob2);
    cudaGetSymbolAddress((void**)&bn,   g_bn);

    cudaFuncSetAttribute(k_offt,       cudaFuncAttributeMaxDynamicSharedMemorySize, OT2_SMEM);
    cudaFuncSetAttribute(k_dcn<false>, cudaFuncAttributeMaxDynamicSharedMemorySize, DCN_SMEM);
    cudaFuncSetAttribute(k_dcn<true>,  cudaFuncAttributeMaxDynamicSharedMemorySize, DCN_SMEM);

    // launch order: k_dcn layer-1 is launch #4 (ncu effective skip = 3)
    k_prep<<<432, 256>>>(w1, w2, woff1, woff2, g1, be1, m1, v1, g2, be2, m2, v2);
    k_nchw2nhwc<<<BATCH*HH, 256>>>(x, xn);
    k_offt<<<BATCH*HH, 256, OT2_SMEM>>>(xn, wob1, boff1, offb);
    k_dcn<false><<<BATCH*HH, 384, DCN_SMEM>>>(xn, offb, wtb1, bn, y1);

    k_offt<<<BATCH*HH, 256, OT2_SMEM>>>(y1, wob2, boff2, offb);
    k_dcn<true><<<BATCH*HH, 384, DCN_SMEM>>>(y1, offb, wtb2, bn + 128, out);
}

// round 11
// speedup vs baseline: 1.2680x; 1.2680x over previous
#include <cuda_runtime.h>
#include <cuda_bf16.h>
#include <cuda_fp16.h>
#include <cstdint>

#define HH 128
#define WW 128
#define CH 64
#define BATCH 4
#define EPS 1e-5f

// ---------------- scratch (no mallocs allowed) ----------------
__device__ __align__(16) float g_xnhwc[BATCH*HH*WW*CH];
__device__ __align__(16) float g_y1   [BATCH*HH*WW*CH];
__device__ __align__(16) float g_off  [BATCH*HH*WW*18];   // layout [bh][18][128]
__device__ __align__(1024) __nv_bfloat16 g_wtb1[9*2*64*64];  // fp16 bits: hi/mid per tap
__device__ __align__(1024) __nv_bfloat16 g_wtb2[9*2*64*64];
__device__ __align__(1024) __nv_bfloat16 g_wob1[9*2*32*64];  // bf16 hi/mid (offconv)
__device__ __align__(1024) __nv_bfloat16 g_wob2[9*2*32*64];
__device__ __align__(16) float g_bn[256];

// ---------------- helpers ----------------
static __device__ __forceinline__ uint32_t smem_to_u32(const void* p){
    uint32_t a;
    asm("{ .reg .u64 t; cvta.to.shared.u64 t, %1; cvt.u32.u64 %0, t; }" : "=r"(a) : "l"(p));
    return a;
}
#define SWZ128(o) ((o) ^ (((o) >> 3) & 0x70))

#define LDSM4(r, a) \
    asm volatile("ldmatrix.sync.aligned.m8n8.x4.shared.b16 {%0,%1,%2,%3}, [%4];" \
        : "=r"((r)[0]), "=r"((r)[1]), "=r"((r)[2]), "=r"((r)[3]) : "r"(a))

static __device__ __forceinline__ void mma_bf16(float* d, const uint32_t* a, uint32_t b0, uint32_t b1){
    asm volatile("mma.sync.aligned.m16n8k16.row.col.f32.bf16.bf16.f32 "
        "{%0,%1,%2,%3},{%4,%5,%6,%7},{%8,%9},{%0,%1,%2,%3};"
        : "+f"(d[0]), "+f"(d[1]), "+f"(d[2]), "+f"(d[3])
        : "r"(a[0]), "r"(a[1]), "r"(a[2]), "r"(a[3]), "r"(b0), "r"(b1));
}
static __device__ __forceinline__ void mma_f16(float* d, const uint32_t* a, uint32_t b0, uint32_t b1){
    asm volatile("mma.sync.aligned.m16n8k16.row.col.f32.f16.f16.f32 "
        "{%0,%1,%2,%3},{%4,%5,%6,%7},{%8,%9},{%0,%1,%2,%3};"
        : "+f"(d[0]), "+f"(d[1]), "+f"(d[2]), "+f"(d[3])
        : "r"(a[0]), "r"(a[1]), "r"(a[2]), "r"(a[3]), "r"(b0), "r"(b1));
}

#define CP_ASYNC16(dst, src) \
    asm volatile("cp.async.cg.shared.global [%0], [%1], 16;" :: "r"(dst), "l"(src) : "memory")
#define CP_COMMIT() asm volatile("cp.async.commit_group;" ::: "memory")
#define CP_WAIT0()  asm volatile("cp.async.wait_group 0;" ::: "memory")

// ---------------- prep ----------------
__global__ void k_prep(const float* __restrict__ w1, const float* __restrict__ w2,
                       const float* __restrict__ woff1, const float* __restrict__ woff2,
                       const float* g1, const float* be1, const float* m1, const float* v1,
                       const float* g2, const float* be2, const float* m2, const float* v2)
{
    int i = blockIdx.x*blockDim.x + threadIdx.x;
    if(i < 73728){
        // main conv weights -> fp16 hi/mid per-tap SW128 tiles
        int L   = i / 36864;
        int rem = i % 36864;
        int k = rem >> 12;
        int o = (rem >> 6) & 63;
        int c = rem & 63;
        const float* w = L ? w2 : w1;
        float val = w[(o*64 + c)*9 + k];
        __half hb = __float2half_rn(val);
        float hf = __half2float(hb);
        __half mb = __float2half_rn(val - hf);
        char* dst = (char*)(L ? g_wtb2 : g_wtb1);
        int sw = SWZ128(o*128 + c*2);
        *(__half*)(dst + k*16384 +        sw) = hb;
        *(__half*)(dst + k*16384 + 8192 + sw) = mb;
    } else if(i < 110592){
        // offset conv weights (bf16 hi/mid, unchanged)
        int j   = i - 73728;
        int L   = j / 18432;
        int rem = j % 18432;
        int k = rem >> 11;
        int o = (rem >> 6) & 31;
        int c = rem & 63;
        const float* w = L ? woff2 : woff1;
        float val = (o < 18) ? w[(o*64 + c)*9 + k] : 0.f;
        __nv_bfloat16 hb = __float2bfloat16(val);
        float hf = __bfloat162float(hb);
        __nv_bfloat16 mb = __float2bfloat16(val - hf);
        char* dst = (char*)(L ? g_wob2 : g_wob1);
        int sw = SWZ128(o*128 + c*2);
        *(__nv_bfloat16*)(dst + k*8192 +        sw) = hb;
        *(__nv_bfloat16*)(dst + k*8192 + 4096 + sw) = mb;
    }
    if(blockIdx.x == 0 && threadIdx.x < 64){
        int t = threadIdx.x;
        float i1 = g1[t] * rsqrtf(v1[t] + EPS);
        g_bn[t]      = i1;
        g_bn[64+t]   = be1[t] - m1[t]*i1;
        float i2 = g2[t] * rsqrtf(v2[t] + EPS);
        g_bn[128+t]  = i2;
        g_bn[192+t]  = be2[t] - m2[t]*i2;
    }
}

// ---------------- NCHW -> NHWC transpose ----------------
__global__ void k_nchw2nhwc(const float* __restrict__ x, float* __restrict__ xn){
    __shared__ float tile[64*129];
    int b = blockIdx.x >> 7;
    int h = blockIdx.x & 127;
    const float* src = x + (b*CH*HH)*WW + h*WW;
    for(int i = threadIdx.x; i < CH*WW; i += blockDim.x){
        int c = i >> 7, w = i & 127;
        tile[c*129 + w] = src[c*HH*WW + w];
    }
    __syncthreads();
    float* dst = xn + ((b*HH + h)*WW)*CH;
    for(int i = threadIdx.x; i < CH*WW; i += blockDim.x){
        int w = i >> 6, c = i & 63;
        dst[w*CH + c] = tile[c*129 + w];
    }
}

// ---------------- offset conv v2 (bf16 3-term, unchanged) ----------------
#define OT2_A_HI  0
#define OT2_A_MID 16640
#define OT2_B     33280
#define OT2_SMEM  49664

__global__ void __launch_bounds__(256,3) k_offt(
    const float* __restrict__ xn, const __nv_bfloat16* __restrict__ wob,
    const float* __restrict__ boff, float* __restrict__ off)
{
    extern __shared__ char smc[];
    const uint32_t smem_base = smem_to_u32(smc);

    const int b = blockIdx.x >> 7;
    const int h = blockIdx.x & 127;
    const int tid = threadIdx.x;
    const int wid = tid >> 5;
    const int lid = tid & 31;
    const int m0 = wid * 16;

    const uint32_t aKh = (lid >> 4) * 16;
    const int aR = m0 + (lid & 15);
    uint32_t bRow[2], bXor[2];
    #pragma unroll
    for(int ni = 0; ni < 2; ni++){
        int r = ni*16 + (lid & 7) + ((lid >> 4) << 3);
        bRow[ni] = r*128;
        bXor[ni] = (r & 7) << 4;
    }
    const uint32_t bKh = ((lid >> 3) & 1) * 16;

    float acc[3][4];
    #pragma unroll
    for(int n8 = 0; n8 < 3; n8++)
        #pragma unroll
        for(int j = 0; j < 4; j++) acc[n8][j] = 0.f;

    {
        const char* bs = (const char*)wob;
        #pragma unroll
        for(int j = 0; j < 2; j++)
            CP_ASYNC16(smem_base + OT2_B + tid*16 + j*4096, bs + tid*16 + j*4096);
        CP_COMMIT();
    }

    #pragma unroll 1
    for(int ky = 0; ky < 3; ky++){
        __syncthreads();
        const int hh = h + ky - 1;
        const bool hv = (hh >= 0) && (hh < HH);
        const float* rowp = xn + (size_t)(b*HH + hh)*WW*CH;
        #pragma unroll 1
        for(int idx = tid; idx < 2080; idx += 256){
            int rho = idx >> 4, q = idx & 15;
            int px = rho - 1;
            float4 v = make_float4(0.f,0.f,0.f,0.f);
            if(hv && px >= 0 && px < WW)
                v = __ldg((const float4*)(rowp + px*CH) + q);
            __nv_bfloat162 h0 = __float22bfloat162_rn(make_float2(v.x, v.y));
            __nv_bfloat162 h1 = __float22bfloat162_rn(make_float2(v.z, v.w));
            float2 f0 = __bfloat1622float2(h0);
            float2 f1 = __bfloat1622float2(h1);
            __nv_bfloat162 m0b = __float22bfloat162_rn(make_float2(v.x - f0.x, v.y - f0.y));
            __nv_bfloat162 m1b = __float22bfloat162_rn(make_float2(v.z - f1.x, v.w - f1.y));
            int sw = SWZ128(rho*128 + q*8);
            uint2 uh, um;
            uh.x = *(uint32_t*)&h0;  uh.y = *(uint32_t*)&h1;
            um.x = *(uint32_t*)&m0b; um.y = *(uint32_t*)&m1b;
            *(uint2*)(smc + OT2_A_HI  + sw) = uh;
            *(uint2*)(smc + OT2_A_MID + sw) = um;
        }

        #pragma unroll 1
        for(int kx = 0; kx < 3; kx++){
            int k = ky*3 + kx;
            CP_WAIT0();
            __syncthreads();
            if(k < 8){
                const char* bs = (const char*)wob + (k+1)*8192;
                uint32_t bd = smem_base + OT2_B + ((k+1)&1)*8192;
                #pragma unroll
                for(int j = 0; j < 2; j++)
                    CP_ASYNC16(bd + tid*16 + j*4096, bs + tid*16 + j*4096);
                CP_COMMIT();
            }
            const uint32_t slotB = smem_base + OT2_B + (k&1)*8192;
            const int rho = aR + 1 + kx - 1;
            const uint32_t aAddrBase = smem_base + OT2_A_HI + rho*128;
            const uint32_t aXor = (rho & 7) << 4;

            #pragma unroll
            for(int ks = 0; ks < 4; ks++){
                uint32_t ahi[4], ami[4], bhi[2][4], bmi[2][4];
                uint32_t ad = aAddrBase + ((ks*32 + aKh) ^ aXor);
                LDSM4(ahi, ad);
                LDSM4(ami, ad + (OT2_A_MID - OT2_A_HI));
                uint32_t cb = ks*32 + bKh;
                #pragma unroll
                for(int ni = 0; ni < 2; ni++){
                    uint32_t bd = slotB + bRow[ni] + (cb ^ bXor[ni]);
                    LDSM4(bhi[ni], bd);
                    LDSM4(bmi[ni], bd + 4096);
                }
                #pragma unroll
                for(int n8 = 0; n8 < 3; n8++){
                    uint32_t bh0 = bhi[n8>>1][(n8&1)*2], bh1 = bhi[n8>>1][(n8&1)*2+1];
                    uint32_t bm0 = bmi[n8>>1][(n8&1)*2], bm1 = bmi[n8>>1][(n8&1)*2+1];
                    mma_bf16(acc[n8], ahi, bh0, bh1);
                    mma_bf16(acc[n8], ahi, bm0, bm1);
                    mma_bf16(acc[n8], ami, bh0, bh1);
                }
            }
        }
    }

    const int r0 = m0 + (lid >> 2);
    const int r1 = r0 + 8;
    float* base = off + (size_t)(b*HH + h)*2304;
    #pragma unroll
    for(int n8 = 0; n8 < 3; n8++){
        int c0 = n8*8 + (lid & 3)*2;
        if(c0 < 18){
            float b0 = __ldg(boff + c0);
            float b1v = __ldg(boff + c0 + 1);
            base[c0*128 + r0]     = acc[n8][0] + b0;
            base[(c0+1)*128 + r0] = acc[n8][1] + b1v;
            base[c0*128 + r1]     = acc[n8][2] + b0;
            base[(c0+1)*128 + r1] = acc[n8][3] + b1v;
        }
    }
}

// ---------------- main DCN v9: fp16 A (single) x fp16 B (hi+mid), v4 pipeline ----------------
#define TB_W_OFF  0          /* float4 wtab[1152] = 18432 (premasked w00..w11) */
#define TB_I_OFF  18432      /* uint  itab[1152] = 4608 */
#define A_OFF     23040      /* 2 x 16384 fp16 A (dbl buf) */
#define B_OFF     55808      /* 2 x (hi 8192 + mid 8192) */
#define DCN_SMEM  88576

template<bool NCHW_OUT>
__global__ void __launch_bounds__(256,2) k_dcn(
    const float* __restrict__ xn, const float* __restrict__ off,
    const __nv_bfloat16* __restrict__ wtb, const float* __restrict__ bn,
    float* __restrict__ out)
{
    extern __shared__ char smc[];
    const uint32_t smem_base = smem_to_u32(smc);

    const int b = blockIdx.x >> 7;
    const int h = blockIdx.x & 127;
    const int tid = threadIdx.x;
    const int wid = tid >> 5;
    const int lid = tid & 31;
    const float fh = (float)h;

    // prefetch B(0): 16KB via cp.async
    {
        const char* bs = (const char*)wtb;
        #pragma unroll
        for(int j = 0; j < 4; j++)
            CP_ASYNC16(smem_base + B_OFF + tid*16 + j*4096, bs + tid*16 + j*4096);
        CP_COMMIT();
    }

    // ---------- build fully-decoded gather table ----------
    {
        float4*   wtab = (float4*)(smc + TB_W_OFF);
        uint32_t* itab = (uint32_t*)(smc + TB_I_OFF);
        const float* offb2 = off + (size_t)(b*HH + h)*2304;
        #pragma unroll 1
        for(int e = tid; e < 1152; e += 256){
            int k  = e >> 7;
            int px = e & 127;
            float dy = __ldg(offb2 + (2*k)*128 + px);
            float dx = __ldg(offb2 + (2*k+1)*128 + px);
            float py  = fh + (float)(k/3 - 1) + dy;
            float pxx = (float)(px + k%3 - 1) + dx;
            float y0f = floorf(py), x0f = floorf(pxx);
            float wy1 = py - y0f,  wx1 = pxx - x0f;
            float wy0 = 1.f - wy1, wx0 = 1.f - wx1;
            bool vy0 = (y0f >= 0.f)  && (y0f <= 127.f);
            bool vy1 = (y0f >= -1.f) && (y0f <= 126.f);
            bool vx0 = (x0f >= 0.f)  && (x0f <= 127.f);
            bool vx1 = (x0f >= -1.f) && (x0f <= 126.f);
            float ay0 = vy0 ? wy0 : 0.f;
            float ay1 = vy1 ? wy1 : 0.f;
            float ax0 = vx0 ? wx0 : 0.f;
            float ax1 = vx1 ? wx1 : 0.f;
            uint32_t yi0 = (uint32_t)(int)fminf(fmaxf(y0f,      0.f),127.f);
            uint32_t yi1 = (uint32_t)(int)fminf(fmaxf(y0f + 1.f,0.f),127.f);
            uint32_t xi0 = (uint32_t)(int)fminf(fmaxf(x0f,      0.f),127.f);
            uint32_t xi1 = (uint32_t)(int)fminf(fmaxf(x0f + 1.f,0.f),127.f);
            wtab[e] = make_float4(ay0*ax0, ay0*ax1, ay1*ax0, ay1*ax1);
            itab[e] = yi0 | (yi1 << 7) | (xi0 << 14) | (xi1 << 21);
        }
    }

    const char* xq = (const char*)(xn + (size_t)b*HH*WW*CH) + (tid & 15)*16;
    const int q  = tid & 15;
    const int pg = tid >> 4;

    __syncthreads();  // table visible

    const float4*   wtab = (const float4*)(smc + TB_W_OFF);
    const uint32_t* itab = (const uint32_t*)(smc + TB_I_OFF);

    // gather one pixel of tap k into A buffer `buf` (fp16 single term)
    auto gather_px = [&](int k, int px, int buf){
        int e = k*128 + px;
        float4 wv = wtab[e];
        uint32_t ii = itab[e];
        uint32_t ry0 = (ii & 0x7fu) << 15;
        uint32_t ry1 = ((ii >> 7) & 0x7fu) << 15;
        uint32_t rx0 = ((ii >> 14) & 0x7fu) << 8;
        uint32_t rx1 = ((ii >> 21) & 0x7fu) << 8;
        float4 a  = __ldg((const float4*)(xq + ry0 + rx0));
        float4 b2 = __ldg((const float4*)(xq + ry0 + rx1));
        float4 c  = __ldg((const float4*)(xq + ry1 + rx0));
        float4 d  = __ldg((const float4*)(xq + ry1 + rx1));
        float4 r;
        r.x = wv.x*a.x + wv.y*b2.x + wv.z*c.x + wv.w*d.x;
        r.y = wv.x*a.y + wv.y*b2.y + wv.z*c.y + wv.w*d.y;
        r.z = wv.x*a.z + wv.y*b2.z + wv.z*c.z + wv.w*d.z;
        r.w = wv.x*a.w + wv.y*b2.w + wv.z*c.w + wv.w*d.w;
        __half2 h0 = __float22half2_rn(make_float2(r.x, r.y));
        __half2 h1 = __float22half2_rn(make_float2(r.z, r.w));
        int sw = SWZ128(px*128 + q*8);
        uint2 uh;
        uh.x = *(uint32_t*)&h0;  uh.y = *(uint32_t*)&h1;
        *(uint2*)(smc + A_OFF + buf*16384 + sw) = uh;
    };

    // prologue: gather A(0) into buf 0
    #pragma unroll 2
    for(int i = 0; i < 8; i++) gather_px(0, pg*8 + i, 0);

    // mma mapping: warp (4 x 2) grid of 32x32 tiles
    const int m0 = (wid >> 1) * 32;
    const int n0 = (wid & 1) * 32;

    uint32_t aRow[2], aXor[2];
    #pragma unroll
    for(int mi = 0; mi < 2; mi++){
        int r = m0 + mi*16 + (lid & 15);
        aRow[mi] = r*128;
        aXor[mi] = (r & 7) << 4;
    }
    const uint32_t aKh = (lid >> 4) * 16;
    uint32_t bRow[2], bXor[2];
    #pragma unroll
    for(int ni = 0; ni < 2; ni++){
        int r = n0 + ni*16 + (lid & 7) + ((lid >> 4) << 3);
        bRow[ni] = r*128;
        bXor[ni] = (r & 7) << 4;
    }
    const uint32_t bKh = ((lid >> 3) & 1) * 16;

    float acc[2][4][4];
    #pragma unroll
    for(int mi = 0; mi < 2; mi++)
        #pragma unroll
        for(int ni = 0; ni < 4; ni++)
            #pragma unroll
            for(int j = 0; j < 4; j++) acc[mi][ni][j] = 0.f;

    int cur = 0;
    #pragma unroll 1
    for(int k = 0; k < 9; k++){
        CP_WAIT0();          // B(k) landed
        __syncthreads();     // A(k) + B(k) visible; A(k-1)/B(k-1) slots free
        if(k < 8){
            const char* bs = (const char*)wtb + (k+1)*16384;
            uint32_t bd = smem_base + B_OFF + ((k+1)&1)*16384;
            #pragma unroll
            for(int j = 0; j < 4; j++)
                CP_ASYNC16(bd + tid*16 + j*4096, bs + tid*16 + j*4096);
            CP_COMMIT();
        }
        const uint32_t aB    = smem_base + A_OFF + cur*16384;
        const uint32_t slotB = smem_base + B_OFF + (k&1)*16384;

        #pragma unroll
        for(int ks = 0; ks < 4; ks++){
            uint32_t ca = ks*32 + aKh;
            uint32_t cb = ks*32 + bKh;
            uint32_t ah[2][4], bh[2][4], bm[2][4];
            #pragma unroll
            for(int mi = 0; mi < 2; mi++)
                LDSM4(ah[mi], aB + aRow[mi] + (ca ^ aXor[mi]));
            #pragma unroll
            for(int ni = 0; ni < 2; ni++){
                uint32_t bd = slotB + bRow[ni] + (cb ^ bXor[ni]);
                LDSM4(bh[ni], bd);
                LDSM4(bm[ni], bd + 8192);
            }
            // gather 2 px of next tap (LDG latency hidden behind the MMAs below)
            if(k < 8){
                gather_px(k+1, pg*8 + ks*2,     cur ^ 1);
                gather_px(k+1, pg*8 + ks*2 + 1, cur ^ 1);
            }
            #pragma unroll
            for(int mi = 0; mi < 2; mi++)
                #pragma unroll
                for(int n8 = 0; n8 < 4; n8++){
                    mma_f16(acc[mi][n8], ah[mi], bh[n8>>1][(n8&1)*2], bh[n8>>1][(n8&1)*2+1]);
                    mma_f16(acc[mi][n8], ah[mi], bm[n8>>1][(n8&1)*2], bm[n8>>1][(n8&1)*2+1]);
                }
        }
        cur ^= 1;
    }

    // epilogue: BN + ReLU + store
    #pragma unroll
    for(int mi = 0; mi < 2; mi++){
        int r0 = m0 + mi*16 + (lid >> 2);
        int r1 = r0 + 8;
        #pragma unroll
        for(int n8 = 0; n8 < 4; n8++){
            int c0 = n0 + n8*8 + (lid & 3)*2;
            float iv0 = __ldg(bn + c0),      iv1 = __ldg(bn + c0 + 1);
            float bc0 = __ldg(bn + 64 + c0), bc1 = __ldg(bn + 64 + c0 + 1);
            float v00 = fmaxf(acc[mi][n8][0]*iv0 + bc0, 0.f);
            float v01 = fmaxf(acc[mi][n8][1]*iv1 + bc1, 0.f);
            float v10 = fmaxf(acc[mi][n8][2]*iv0 + bc0, 0.f);
            float v11 = fmaxf(acc[mi][n8][3]*iv1 + bc1, 0.f);
            if(NCHW_OUT){
                float* o0 = out + (((size_t)b*CH + c0)*HH + h)*WW;
                float* o1 = out + (((size_t)b*CH + c0+1)*HH + h)*WW;
                o0[r0] = v00; o1[r0] = v01;
                o0[r1] = v10; o1[r1] = v11;
            } else {
                float* base = out + ((size_t)(b*HH + h)*WW)*CH;
                *(float2*)(base + r0*CH + c0) = make_float2(v00, v01);
                *(float2*)(base + r1*CH + c0) = make_float2(v10, v11);
            }
        }
    }
}

// ---------------- launcher ----------------
extern "C" void kernel_launch(void* const* d_in, const int* in_sizes, int n_in,
                              void* d_out, int out_size)
{
    const float* x     = (const float*)d_in[0];
    const float* woff1 = (const float*)d_in[1];
    const float* boff1 = (const float*)d_in[2];
    const float* w1    = (const float*)d_in[3];
    const float* g1    = (const float*)d_in[4];
    const float* be1   = (const float*)d_in[5];
    const float* m1    = (const float*)d_in[6];
    const float* v1    = (const float*)d_in[7];
    const float* woff2 = (const float*)d_in[8];
    const float* boff2 = (const float*)d_in[9];
    const float* w2    = (const float*)d_in[10];
    const float* g2    = (const float*)d_in[11];
    const float* be2   = (const float*)d_in[12];
    const float* m2    = (const float*)d_in[13];
    const float* v2    = (const float*)d_in[14];
    float* out = (float*)d_out;

    float *xn, *y1, *offb, *bn;
    __nv_bfloat16 *wtb1, *wtb2, *wob1, *wob2;
    cudaGetSymbolAddress((void**)&xn,   g_xnhwc);
    cudaGetSymbolAddress((void**)&y1,   g_y1);
    cudaGetSymbolAddress((void**)&offb, g_off);
    cudaGetSymbolAddress((void**)&wtb1, g_wtb1);
    cudaGetSymbolAddress((void**)&wtb2, g_wtb2);
    cudaGetSymbolAddress((void**)&wob1, g_wob1);
    cudaGetSymbolAddress((void**)&wob2, g_wob2);
    cudaGetSymbolAddress((void**)&bn,   g_bn);

    cudaFuncSetAttribute(k_offt,       cudaFuncAttributeMaxDynamicSharedMemorySize, OT2_SMEM);
    cudaFuncSetAttribute(k_dcn<false>, cudaFuncAttributeMaxDynamicSharedMemorySize, DCN_SMEM);
    cudaFuncSetAttribute(k_dcn<true>,  cudaFuncAttributeMaxDynamicSharedMemorySize, DCN_SMEM);

    // launch order: k_dcn layer-1 is launch #4 (ncu effective skip = 3)
    k_prep<<<432, 256>>>(w1, w2, woff1, woff2, g1, be1, m1, v1, g2, be2, m2, v2);
    k_nchw2nhwc<<<BATCH*HH, 256>>>(x, xn);
    k_offt<<<BATCH*HH, 256, OT2_SMEM>>>(xn, wob1, boff1, offb);
    k_dcn<false><<<BATCH*HH, 256, DCN_SMEM>>>(xn, offb, wtb1, bn, y1);

    k_offt<<<BATCH*HH, 256, OT2_SMEM>>>(y1, wob2, boff2, offb);
    k_dcn<true><<<BATCH*HH, 256, DCN_SMEM>>>(y1, offb, wtb2, bn + 128, out);
}